// round 11
// baseline (speedup 1.0000x reference)
#include <cuda_runtime.h>

#define B 8
#define A 65536
#define C 80
#define G 16
#define TOPK 50
#define NB 4096
#define BSH 18
#define CANDC 2048
#define KS_BLOCKS 128
#define KA_BLOCKS 2048
#define KN_BLOCKS 6144
#define KD_BLOCKS 256

typedef unsigned long long u64;

// ------------------------- static device scratch -------------------------
__device__ unsigned g_maxiou[B * G];     // max decoded IoU (bits)
__device__ int      g_nrec;              // sparse record count
__device__ unsigned g_rec[B * A];        // sparse records (b<<16 | a)
__device__ double   g_sums[2];           // [0]=pos, [1]=neg

// ------------------------------ helpers ---------------------------------
// _rn-pinned ops: all IoU computations are bitwise identical across call sites.
struct Corners { float x0, y0, x1, y1, area; };

__device__ __forceinline__ Corners corners_rn(const float4 p) {
    Corners c;
    c.x0 = __fmaf_rn(-0.5f, p.z, p.x);
    c.y0 = __fmaf_rn(-0.5f, p.w, p.y);
    c.x1 = __fmaf_rn( 0.5f, p.z, p.x);
    c.y1 = __fmaf_rn( 0.5f, p.w, p.y);
    c.area = __fmul_rn(p.z, p.w);
    return c;
}

__device__ __forceinline__ float iou_ct(const Corners c, const float4 t, float tA) {
    float iw = fmaxf(__fsub_rn(fminf(c.x1, t.z), fmaxf(c.x0, t.x)), 0.f);
    float ih = fmaxf(__fsub_rn(fminf(c.y1, t.w), fmaxf(c.y0, t.y)), 0.f);
    float inter = __fmul_rn(iw, ih);
    if (inter <= 0.f) return 0.f;
    return __fdividef(inter, __fsub_rn(__fadd_rn(tA, c.area), inter));
}

__device__ __forceinline__ float fiou_rn(const float4 t, float tA,
                                         float bx0, float by0, float bx1, float by1, float bA) {
    float iw = fmaxf(__fsub_rn(fminf(t.z, bx1), fmaxf(t.x, bx0)), 0.f);
    float ih = fmaxf(__fsub_rn(fminf(t.w, by1), fmaxf(t.y, by0)), 0.f);
    float inter = __fmul_rn(iw, ih);
    if (inter <= 0.f) return 0.f;
    return __fdividef(inter, __fsub_rn(__fadd_rn(tA, bA), inter));
}

__device__ __forceinline__ float fastrcp(float s) {
    float r = __uint_as_float(0x7EF311C3u - __float_as_uint(s));
    r = r * (2.f - s * r);
    r = r * (2.f - s * r);
    r = r * (2.f - s * r);
    return r;
}

// sigmoid(x)^2 * softplus(x): 2 MUFU (EX2 + LG2)
__device__ __forceinline__ float negterm(float x) {
    float e = __expf(x);
    float s = 1.f + e;
    float p = e * fastrcp(s);
    return p * p * __logf(s);
}

__device__ __forceinline__ float sl1(float v) {
    float av = fabsf(v);
    return (av < 0.11f) ? 4.5454545454545450f * v * v : av - 0.055f;
}

__device__ __forceinline__ float blockReduceSum(float v) {
    __shared__ float s[32];
    int lane = threadIdx.x & 31, wid = threadIdx.x >> 5;
    #pragma unroll
    for (int o = 16; o; o >>= 1) v += __shfl_down_sync(0xffffffffu, v, o);
    if (lane == 0) s[wid] = v;
    __syncthreads();
    int nw = (blockDim.x + 31) >> 5;
    v = (threadIdx.x < nw) ? s[threadIdx.x] : 0.f;
    if (wid == 0) {
        #pragma unroll
        for (int o = 16; o; o >>= 1) v += __shfl_down_sync(0xffffffffu, v, o);
    }
    return v; // valid in thread 0
}

// ------------------------------ kernels ---------------------------------
__global__ void kI() {
    int i = threadIdx.x;
    if (i < B * G) g_maxiou[i] = 0u;
    if (i == 0) { g_sums[0] = 0.0; g_sums[1] = 0.0; g_nrec = 0; }
}

// Fused mega-kernel:
//  blocks [0, KS_BLOCKS):                 per-bg top-50 select + positive bag loss
//  blocks [KS, KS+KA_BLOCKS):             per-anchor decoded-IoU pass (t2 max + records)
//  blocks [KS+KA, KS+KA+KN_BLOCKS):       dense negative loss over logits
__global__ void kAN(const float4* __restrict__ br, const float4* __restrict__ anc,
                    const float4* __restrict__ tbx, const int* __restrict__ lab,
                    const float* __restrict__ logits) {
    __shared__ __align__(16) unsigned char sbig[NB * 4];  // hist u32[NB] | cand u64[CANDC]
    __shared__ unsigned sp[256];
    __shared__ unsigned ssel[TOPK];
    __shared__ float swv[TOPK], swl[TOPK];
    __shared__ int scc, scount, stbin;
    __shared__ float4 st[G];
    __shared__ float  sta[G];
    __shared__ unsigned smax[G];

    int tid = threadIdx.x;

    if (blockIdx.x < KS_BLOCKS) {
        // ---------------- SELECT branch: one block per (b,g) ----------------
        unsigned* hist = (unsigned*)sbig;
        u64* cand = (u64*)sbig;
        int bg = blockIdx.x;
        int b = bg >> 4, g = bg & 15;
        float4 t = tbx[bg];
        float tA = __fmul_rn(__fsub_rn(t.z, t.x), __fsub_rn(t.w, t.y));

        for (int i = tid; i < NB; i += 256) hist[i] = 0u;
        if (tid == 0) { scc = 0; scount = 0; }
        __syncthreads();

        // phase A: histogram of anchor-form IoU over all anchors
        for (int a = tid; a < A; a += 256) {
            Corners ac = corners_rn(anc[a]);
            float mi = iou_ct(ac, t, tA);
            if (mi > 0.f) atomicAdd(&hist[__float_as_uint(mi) >> BSH], 1u);
        }
        __syncthreads();

        // phase B: threshold bin (largest suffix with count >= TOPK)
        unsigned accp = 0;
        #pragma unroll
        for (int i = 0; i < NB / 256; i++) accp += hist[tid * (NB / 256) + i];
        sp[tid] = accp;
        __syncthreads();
        if (tid == 0) {
            int cum = 0, tb = 0;
            for (int c = 255; c >= 0; c--) {
                if (cum + (int)sp[c] >= TOPK) {
                    int base = c * (NB / 256);
                    for (int i = NB / 256 - 1; i >= 0; i--) {
                        cum += (int)hist[base + i];
                        if (cum >= TOPK) { tb = base + i; break; }
                    }
                    break;
                }
                cum += (int)sp[c];
            }
            stbin = tb;
        }
        __syncthreads();
        float thrf = __uint_as_float((unsigned)stbin << BSH);
        __syncthreads();   // all done reading hist before it becomes cand

        // phase C: rescan, collect candidate keys (superset of exact top-50)
        for (int a = tid; a < A; a += 256) {
            Corners ac = corners_rn(anc[a]);
            float mi = iou_ct(ac, t, tA);
            if (mi > 0.f && mi >= thrf) {
                int pos = atomicAdd(&scc, 1);
                if (pos < CANDC)
                    cand[pos] = ((u64)__float_as_uint(mi) << 32) | (unsigned)(~(unsigned)a);
            }
        }
        __syncthreads();
        int cc = min(scc, CANDC);

        // phase D: exact rank top-50 (value desc, index asc)
        for (int i = tid; i < cc; i += 256) {
            u64 k = cand[i];
            int r = 0;
            for (int j = 0; j < cc; j++) r += (cand[j] > k);
            if (r < TOPK) {
                int s = atomicAdd(&scount, 1);
                ssel[s] = ~(unsigned)(k & 0xffffffffu);
            }
        }
        __syncthreads();
        // deficit: fewer than 50 positive-IoU anchors -> zero-IoU anchors, index asc
        if (scount < TOPK && tid == 0) {
            int n = scount, need = TOPK - n;
            for (int a = 0; a < A && need > 0; a++) {
                Corners ac = corners_rn(anc[a]);
                float mi = iou_ct(ac, t, tA);
                if (mi <= 0.f) { ssel[n++] = (unsigned)a; need--; }
            }
            scount = n;
        }
        __syncthreads();
        int n = scount;

        // phase F: positive bag loss epilogue
        if (tid < n) {
            unsigned a = ssel[tid];
            float4 p = anc[a];
            float4 l = br[(size_t)b * A + a];
            int lbl = lab[bg];
            float xl = logits[((size_t)(b * A) + a) * C + lbl];
            float e = __expf(xl);
            float mcp = __fdividef(e, 1.f + e);
            float gx = __fdividef((t.x + t.z) * 0.5f - p.x, 0.1f * p.z);
            float gy = __fdividef((t.y + t.w) * 0.5f - p.y, 0.1f * p.w);
            float gw = __logf(__fdividef(t.z - t.x, p.z)) * 5.0f;
            float gh = __logf(__fdividef(t.w - t.y, p.w)) * 5.0f;
            float reg = 0.75f * (sl1(gx - l.x) + sl1(gy - l.y) + sl1(gw - l.z) + sl1(gh - l.w));
            float mbp = __expf(-reg);
            float li = mcp * mbp;
            float w = __fdividef(1.f, fmaxf(1.f - li, 1e-12f));
            swv[tid] = w;
            swl[tid] = w * li;
        }
        __syncthreads();
        if (tid == 0 && n > 0) {
            float sw = 0.f, sl = 0.f;
            for (int i = 0; i < n; i++) { sw += swv[i]; sl += swl[i]; }
            float bag = __fdividef(sl, sw);
            atomicAdd(&g_sums[0], (double)(-__logf(bag)));
        }
    } else if (blockIdx.x < KS_BLOCKS + KA_BLOCKS) {
        // ---------------- A branch: decoded IoU, t2 max, sparse records ----------------
        int bx = blockIdx.x - KS_BLOCKS;
        int b = bx >> 8;
        int a = ((bx & 255) << 8) | tid;
        if (tid < G) {
            float4 t = tbx[b * G + tid];
            st[tid] = t;
            sta[tid] = __fmul_rn(__fsub_rn(t.z, t.x), __fsub_rn(t.w, t.y));
            smax[tid] = 0u;
        }
        __syncthreads();

        float4 l = br[b * A + a];
        float4 p = anc[a];
        float dcx = p.x + l.x * 0.1f * p.z;
        float dcy = p.y + l.y * 0.1f * p.w;
        float dw  = p.z * __expf(l.z * 0.2f);
        float dh  = p.w * __expf(l.w * 0.2f);
        float dx0 = dcx - 0.5f * dw, dy0 = dcy - 0.5f * dh;
        float dx1 = dcx + 0.5f * dw, dy1 = dcy + 0.5f * dh;
        float dA  = dw * dh;

        float dmax = 0.f;
        #pragma unroll
        for (int g = 0; g < G; g++) {
            float di = fiou_rn(st[g], sta[g], dx0, dy0, dx1, dy1, dA);
            dmax = fmaxf(dmax, di);
            unsigned db = __float_as_uint(di);
            if (db > smax[g]) atomicMax(&smax[g], db);   // read-filtered max
        }
        if (dmax > 0.49f) {                              // margin vs recompute drift
            int pos = atomicAdd(&g_nrec, 1);
            g_rec[pos] = ((unsigned)b << 16) | (unsigned)a;
        }
        __syncthreads();
        if (tid < G) atomicMax(&g_maxiou[b * G + tid], smax[tid]);
    } else {
        // ---------------- NEG branch: dense negative loss ----------------
        const float4* logits4 = (const float4*)logits;
        const int n4 = B * A * C / 4;
        int bid = blockIdx.x - (KS_BLOCKS + KA_BLOCKS);
        float acc = 0.f;
        for (int i = bid * 256 + tid; i < n4; i += KN_BLOCKS * 256) {
            float4 v = logits4[i];
            acc += negterm(v.x) + negterm(v.y) + negterm(v.z) + negterm(v.w);
        }
        float tot = blockReduceSum(acc);
        if (tid == 0) atomicAdd(&g_sums[1], (double)tot);
    }
}

// Sparse negative-loss correction (invden computed inline from g_maxiou)
__global__ void kD(const float4* __restrict__ br, const float4* __restrict__ anc,
                   const float4* __restrict__ tbx, const int* __restrict__ lab,
                   const float* __restrict__ logits) {
    __shared__ float4 st[B * G];
    __shared__ float  sta[B * G];
    __shared__ float  sinv[B * G];
    __shared__ int    slbl[B * G];
    __shared__ int    sfirst[B * G];
    if (threadIdx.x < B * G) {
        float4 t = tbx[threadIdx.x];
        st[threadIdx.x] = t;
        sta[threadIdx.x] = __fmul_rn(__fsub_rn(t.z, t.x), __fsub_rn(t.w, t.y));
        slbl[threadIdx.x] = lab[threadIdx.x];
        float m = __uint_as_float(g_maxiou[threadIdx.x]);
        sinv[threadIdx.x] = (m > 0.5f) ? __fdividef(1.f, m - 0.5f) : 0.f;
    }
    __syncthreads();
    if (threadIdx.x < B * G) {
        int b = threadIdx.x >> 4, g = threadIdx.x & 15, f = 1;
        for (int j = 0; j < g; j++) if (slbl[b * G + j] == slbl[threadIdx.x]) f = 0;
        sfirst[threadIdx.x] = f;
    }
    __syncthreads();

    int nrec = g_nrec;
    float corr = 0.f;
    for (int i = blockIdx.x * blockDim.x + threadIdx.x; i < nrec; i += KD_BLOCKS * blockDim.x) {
        unsigned rec = g_rec[i];
        int b = rec >> 16;
        int a = rec & 0xffff;
        float4 l = br[b * A + a];
        float4 p = anc[a];
        float dcx = p.x + l.x * 0.1f * p.z;
        float dcy = p.y + l.y * 0.1f * p.w;
        float dw  = p.z * __expf(l.z * 0.2f);
        float dh  = p.w * __expf(l.w * 0.2f);
        float dx0 = dcx - 0.5f * dw, dy0 = dcy - 0.5f * dh;
        float dx1 = dcx + 0.5f * dw, dy1 = dcy + 0.5f * dh;
        float dA  = dw * dh;
        float obp[G];
        #pragma unroll
        for (int g = 0; g < G; g++) {
            int bg = b * G + g;
            float di = fiou_rn(st[bg], sta[bg], dx0, dy0, dx1, dy1, dA);
            obp[g] = fminf(fmaxf((di - 0.5f) * sinv[bg], 0.f), 1.f);
        }
        #pragma unroll
        for (int g = 0; g < G; g++) {
            int bg = b * G + g;
            if (!sfirst[bg]) continue;
            float bp = obp[g];
            #pragma unroll
            for (int j = g + 1; j < G; j++)
                if (slbl[b * G + j] == slbl[bg]) bp = fmaxf(bp, obp[j]);
            if (bp > 0.f) {
                float xl = logits[((size_t)(b * A) + a) * C + slbl[bg]];
                float pt = negterm(xl);               // cancels dense term exactly
                float e = __expf(xl);
                float pp = e * fastrcp(1.f + e);
                float x = pp * (1.f - bp);
                float xt = x * x * (-__logf(1.f - x));
                corr += xt - pt;
            }
        }
    }
    float tot = blockReduceSum(corr);
    if (threadIdx.x == 0 && tot != 0.f) atomicAdd(&g_sums[1], (double)tot);
}

__global__ void kF(float* out) {
    out[0] = (float)(g_sums[0] * (0.5 / 128.0));    // ALPHA / (B*G)
    out[1] = (float)(g_sums[1] * (0.5 / 6400.0));   // (1-ALPHA) / (B*G*TOPK)
}

// ------------------------------ launch -----------------------------------
extern "C" void kernel_launch(void* const* d_in, const int* in_sizes, int n_in,
                              void* d_out, int out_size) {
    const float4* br     = (const float4*)d_in[0];   // box_regression (B,A,4)
    const float*  logits = (const float*) d_in[1];   // cls_logits (B,A,C)
    const float4* anc    = (const float4*)d_in[2];   // anchors (A,4)
    const float4* tbx    = (const float4*)d_in[3];   // targets_boxes (B,G,4)
    const int*    lab    = (const int*)   d_in[4];   // labels (B,G)
    float* out = (float*)d_out;

    kI<<<1, 128>>>();
    kAN<<<KS_BLOCKS + KA_BLOCKS + KN_BLOCKS, 256>>>(br, anc, tbx, lab, logits);
    kD<<<KD_BLOCKS, 256>>>(br, anc, tbx, lab, logits);
    kF<<<1, 1>>>(out);
}